// round 14
// baseline (speedup 1.0000x reference)
#include <cuda_runtime.h>
#include <cstdint>

#define NQ     8
#define DIM    256
#define NW     16
#define BATCH  16
#define NROTS  64
#define EMB    512
#define VOCAB  50257
#define NM     24

typedef unsigned long long ull;

/* ---------------- scratch (device globals) ------------------------------- */
__device__ float  g_fp[BATCH];
__device__ float  g_h[BATCH * EMB];
__device__ float2 g_cs[BATCH * NW * NROTS];

/* ---------------- packed f32x2 helpers ----------------------------------- */
__device__ __forceinline__ ull fma2(ull a, ull b, ull c) {
    ull d;
    asm("fma.rn.f32x2 %0, %1, %2, %3;" : "=l"(d) : "l"(a), "l"(b), "l"(c));
    return d;
}
__device__ __forceinline__ ull add2(ull a, ull b) {
    ull d;
    asm("add.rn.f32x2 %0, %1, %2;" : "=l"(d) : "l"(a), "l"(b));
    return d;
}
__device__ __forceinline__ float2 upk2(ull v) {
    float lo, hi;
    asm("mov.b64 {%0, %1}, %2;" : "=f"(lo), "=f"(hi) : "l"(v));
    return make_float2(lo, hi);
}
__device__ __forceinline__ ull pack2(float x, float y) {
    ull r;
    asm("mov.b64 %0, {%1, %2};" : "=l"(r) : "f"(x), "f"(y));
    return r;
}

/* ============ warp-level statevector gates (amp i = lane*8 + r) ========== */
__device__ __forceinline__ float2 shfl_xor_f2(float2 v, int m) {
    float2 r;
    r.x = __shfl_xor_sync(0xffffffffu, v.x, m);
    r.y = __shfl_xor_sync(0xffffffffu, v.y, m);
    return r;
}

template<int BP>
__device__ __forceinline__ void ry_reg(float2* v, float c, float s) {
#pragma unroll
    for (int r0 = 0; r0 < 8; r0++) {
        if (r0 & (1 << BP)) continue;
        const int r1 = r0 | (1 << BP);
        float2 a0 = v[r0], a1 = v[r1];
        v[r0] = make_float2(c * a0.x - s * a1.x, c * a0.y - s * a1.y);
        v[r1] = make_float2(s * a0.x + c * a1.x, s * a0.y + c * a1.y);
    }
}
template<int LB>
__device__ __forceinline__ void ry_lane(float2* v, float c, float s, int lane) {
    float ss = ((lane >> LB) & 1) ? s : -s;
#pragma unroll
    for (int r = 0; r < 8; r++) {
        float2 p = shfl_xor_f2(v[r], 1 << LB);
        v[r].x = c * v[r].x + ss * p.x;
        v[r].y = c * v[r].y + ss * p.y;
    }
}
template<int BC, int BT>
__device__ __forceinline__ void crx_rr(float2* v, float c, float s) {
#pragma unroll
    for (int r0 = 0; r0 < 8; r0++) {
        if (!(r0 & (1 << BC)) || (r0 & (1 << BT))) continue;
        const int r1 = r0 | (1 << BT);
        float2 a0 = v[r0], a1 = v[r1];
        v[r0] = make_float2(c * a0.x + s * a1.y, c * a0.y - s * a1.x);
        v[r1] = make_float2(s * a0.y + c * a1.x, -s * a0.x + c * a1.y);
    }
}
template<int LC, int BT>
__device__ __forceinline__ void crx_lr(float2* v, float c, float s, int lane) {
    if ((lane >> LC) & 1) {
#pragma unroll
        for (int r0 = 0; r0 < 8; r0++) {
            if (r0 & (1 << BT)) continue;
            const int r1 = r0 | (1 << BT);
            float2 a0 = v[r0], a1 = v[r1];
            v[r0] = make_float2(c * a0.x + s * a1.y, c * a0.y - s * a1.x);
            v[r1] = make_float2(s * a0.y + c * a1.x, -s * a0.x + c * a1.y);
        }
    }
}
template<int BC, int LT>
__device__ __forceinline__ void crx_rl(float2* v, float c, float s) {
#pragma unroll
    for (int r = 0; r < 8; r++) {
        if (!(r & (1 << BC))) continue;
        float2 p = shfl_xor_f2(v[r], 1 << LT);
        float2 a = v[r];
        v[r].x = c * a.x + s * p.y;
        v[r].y = c * a.y - s * p.x;
    }
}
template<int LC, int LT>
__device__ __forceinline__ void crx_ll(float2* v, float c, float s, int lane) {
    bool act = (lane >> LC) & 1;
#pragma unroll
    for (int r = 0; r < 8; r++) {
        float2 p = shfl_xor_f2(v[r], 1 << LT);
        if (act) {
            float2 a = v[r];
            v[r].x = c * a.x + s * p.y;
            v[r].y = c * a.y - s * p.x;
        }
    }
}

__device__ __forceinline__ void sim_layer(float2* v, const float2* cs, int lane) {
    float2 g;
    g = cs[0];  ry_lane<4>(v, g.x, g.y, lane);
    g = cs[1];  ry_lane<3>(v, g.x, g.y, lane);
    g = cs[2];  ry_lane<2>(v, g.x, g.y, lane);
    g = cs[3];  ry_lane<1>(v, g.x, g.y, lane);
    g = cs[4];  ry_lane<0>(v, g.x, g.y, lane);
    g = cs[5];  ry_reg<2>(v, g.x, g.y);
    g = cs[6];  ry_reg<1>(v, g.x, g.y);
    g = cs[7];  ry_reg<0>(v, g.x, g.y);
    g = cs[8];  crx_rl<0, 4>(v, g.x, g.y);
    g = cs[9];  crx_rr<1, 0>(v, g.x, g.y);
    g = cs[10]; crx_rr<2, 1>(v, g.x, g.y);
    g = cs[11]; crx_lr<0, 2>(v, g.x, g.y, lane);
    g = cs[12]; crx_ll<1, 0>(v, g.x, g.y, lane);
    g = cs[13]; crx_ll<2, 1>(v, g.x, g.y, lane);
    g = cs[14]; crx_ll<3, 2>(v, g.x, g.y, lane);
    g = cs[15]; crx_ll<4, 3>(v, g.x, g.y, lane);
    g = cs[16]; ry_lane<4>(v, g.x, g.y, lane);
    g = cs[17]; ry_lane<3>(v, g.x, g.y, lane);
    g = cs[18]; ry_lane<2>(v, g.x, g.y, lane);
    g = cs[19]; ry_lane<1>(v, g.x, g.y, lane);
    g = cs[20]; ry_lane<0>(v, g.x, g.y, lane);
    g = cs[21]; ry_reg<2>(v, g.x, g.y);
    g = cs[22]; ry_reg<1>(v, g.x, g.y);
    g = cs[23]; ry_reg<0>(v, g.x, g.y);
    g = cs[24]; crx_rr<0, 1>(v, g.x, g.y);
    g = cs[25]; crx_lr<4, 0>(v, g.x, g.y, lane);
    g = cs[26]; crx_ll<3, 4>(v, g.x, g.y, lane);
    g = cs[27]; crx_ll<2, 3>(v, g.x, g.y, lane);
    g = cs[28]; crx_ll<1, 2>(v, g.x, g.y, lane);
    g = cs[29]; crx_ll<0, 1>(v, g.x, g.y, lane);
    g = cs[30]; crx_rl<2, 0>(v, g.x, g.y);
    g = cs[31]; crx_rr<1, 2>(v, g.x, g.y);
}

/* --------- kernel 0: no-op (shifts ncu -s 5 window onto k_ff2) ----------- */
__global__ void k_nop() {}

/* --------- kernel 1: wparams, warp-per-2-rots, emb in registers ---------- */
__global__ void __launch_bounds__(256) k_wparams(const int* __restrict__ x,
                                                 const float* __restrict__ embW,
                                                 const float* __restrict__ e2rW,
                                                 const float* __restrict__ e2rb) {
    int bw = blockIdx.x, tid = threadIdx.x;
    int w = tid >> 5, lane = tid & 31;
    __shared__ float emb[EMB];
    int tok = __ldg(&x[bw]);                       /* broadcast load */
    if (tid < 128)
        reinterpret_cast<float4*>(emb)[tid] =
            reinterpret_cast<const float4*>(embW + (size_t)tok * EMB)[tid];
    __syncthreads();

    const float4* es = reinterpret_cast<const float4*>(emb);
    float4 e0 = es[lane], e1 = es[lane + 32], e2 = es[lane + 64], e3 = es[lane + 96];

#pragma unroll
    for (int jj = 0; jj < 8; jj += 2) {
        int ra = w * 8 + jj;
        const float4* wa = reinterpret_cast<const float4*>(e2rW + (size_t)ra * EMB);
        const float4* wb = reinterpret_cast<const float4*>(e2rW + (size_t)(ra + 1) * EMB);
        float4 a0 = __ldg(&wa[lane]),      a1 = __ldg(&wa[lane + 32]);
        float4 a2 = __ldg(&wa[lane + 64]), a3 = __ldg(&wa[lane + 96]);
        float4 b0 = __ldg(&wb[lane]),      b1 = __ldg(&wb[lane + 32]);
        float4 b2 = __ldg(&wb[lane + 64]), b3 = __ldg(&wb[lane + 96]);
        float accA = a0.x*e0.x + a0.y*e0.y + a0.z*e0.z + a0.w*e0.w
                   + a1.x*e1.x + a1.y*e1.y + a1.z*e1.z + a1.w*e1.w
                   + a2.x*e2.x + a2.y*e2.y + a2.z*e2.z + a2.w*e2.w
                   + a3.x*e3.x + a3.y*e3.y + a3.z*e3.z + a3.w*e3.w;
        float accB = b0.x*e0.x + b0.y*e0.y + b0.z*e0.z + b0.w*e0.w
                   + b1.x*e1.x + b1.y*e1.y + b1.z*e1.z + b1.w*e1.w
                   + b2.x*e2.x + b2.y*e2.y + b2.z*e2.z + b2.w*e2.w
                   + b3.x*e3.x + b3.y*e3.y + b3.z*e3.z + b3.w*e3.w;
#pragma unroll
        for (int off = 16; off; off >>= 1) {
            accA += __shfl_xor_sync(0xffffffffu, accA, off);
            accB += __shfl_xor_sync(0xffffffffu, accB, off);
        }
        if (lane == 0) {
            float pa = accA + e2rb[ra];
            float pb = accB + e2rb[ra + 1];
            g_cs[bw * NROTS + ra]     = make_float2(cosf(0.5f * pa), sinf(0.5f * pa));
            g_cs[bw * NROTS + ra + 1] = make_float2(cosf(0.5f * pb), sinf(0.5f * pb));
        }
    }
}

/* --------- kernel 2: mega (sim 3 degrees + finalize + measure + FF1) ----- */
__global__ void __launch_bounds__(512) k_mega(
    const float* __restrict__ poly,
    const float* __restrict__ mix,
    const float* __restrict__ qff,
    const float* __restrict__ ff1W,
    const float* __restrict__ ff1b)
{
    int b = blockIdx.x, tid = threadIdx.x;
    int w = tid >> 5, lane = tid & 31;

    __shared__ float2 st_sh[NW * DIM];
    __shared__ float2 cs_sh[NW * NROTS];
    __shared__ float2 work[DIM];
    __shared__ float2 acc[DIM];
    __shared__ float2 coeffs[NW];
    __shared__ float2 csf[32];
    __shared__ float  red[8];
    __shared__ float  ex[NM];
    __shared__ float  inv_nrm_sh;

    for (int i = tid; i < NW * NROTS; i += 512)
        cs_sh[i] = g_cs[b * NW * NROTS + i];
    if (tid == 0) {
        float ssum = 0.f;
        for (int k = 0; k < NW; k++) {
            float re = mix[2 * k], im = mix[2 * k + 1];
            ssum += sqrtf(re * re + im * im);
        }
        float inv = 1.0f / fmaxf(ssum, 1e-12f);
        for (int k = 0; k < NW; k++)
            coeffs[k] = make_float2(mix[2 * k] * inv, mix[2 * k + 1] * inv);
    }
    if (tid < 32) {
        float p = qff[tid];
        csf[tid] = make_float2(cosf(0.5f * p), sinf(0.5f * p));
    }
    float p0 = poly[0], p1 = poly[1], p2 = poly[2], p3 = poly[3];
    if (tid < DIM) {
        bool z = (tid == 0);
        work[tid] = z ? make_float2(1.f, 0.f) : make_float2(0.f, 0.f);
        acc[tid]  = z ? make_float2(p0, 0.f)  : make_float2(0.f, 0.f);
    }
    __syncthreads();

#pragma unroll 1
    for (int d = 1; d <= 3; d++) {
        float pd = (d == 1) ? p1 : ((d == 2) ? p2 : p3);
        float2 v[8];
#pragma unroll
        for (int r = 0; r < 8; r++) v[r] = work[lane * 8 + r];

        sim_layer(v, cs_sh + w * NROTS, lane);
        sim_layer(v, cs_sh + w * NROTS + 32, lane);

#pragma unroll
        for (int r = 0; r < 8; r++) st_sh[w * DIM + lane * 8 + r] = v[r];
        __syncthreads();

        if (tid < DIM) {
            float2 s = make_float2(0.f, 0.f);
#pragma unroll
            for (int w2 = 0; w2 < NW; w2++) {
                float2 cw = coeffs[w2];
                float2 u  = st_sh[w2 * DIM + tid];
                s.x += cw.x * u.x - cw.y * u.y;
                s.y += cw.x * u.y + cw.y * u.x;
            }
            work[tid] = s;
            float2 a = acc[tid];
            a.x += pd * s.x; a.y += pd * s.y;
            acc[tid] = a;
        }
        __syncthreads();
    }

    /* normalize */
    float psum = fabsf(p0) + fabsf(p1) + fabsf(p2) + fabsf(p3);
    float inv1 = 1.0f / psum;
    float2 a2 = make_float2(0.f, 0.f);
    float nv = 0.f;
    if (tid < DIM) {
        a2 = acc[tid];
        a2.x *= inv1; a2.y *= inv1;
        nv = a2.x * a2.x + a2.y * a2.y;
    }
    for (int off = 16; off; off >>= 1) nv += __shfl_xor_sync(0xffffffffu, nv, off);
    if (tid < DIM && lane == 0) red[w] = nv;
    __syncthreads();
    if (tid == 0) {
        float s = 0.f;
        for (int k = 0; k < 8; k++) s += red[k];
        float nm = sqrtf(s);
        g_fp[b] = nm;
        inv_nrm_sh = 1.0f / fmaxf(nm, 1e-12f);
    }
    __syncthreads();
    float inv2 = inv_nrm_sh;
    if (tid < DIM) st_sh[tid] = make_float2(a2.x * inv2, a2.y * inv2);
    __syncthreads();

    /* final 32-gate circuit + measurement: warp 0 only */
    if (w == 0) {
        float2 v[8];
#pragma unroll
        for (int r = 0; r < 8; r++) v[r] = st_sh[lane * 8 + r];
        sim_layer(v, csf, lane);

        for (int q = 0; q < NQ; q++) {
            int bp = 7 - q;
            float cre = 0.f, cim = 0.f, zz = 0.f;
            if (bp >= 3) {
                int lb = bp - 3;
                int tb = (lane >> lb) & 1;
#pragma unroll
                for (int r = 0; r < 8; r++) {
                    float2 p = shfl_xor_f2(v[r], 1 << lb);
                    float nn = v[r].x * v[r].x + v[r].y * v[r].y;
                    if (tb == 0) {
                        cre += v[r].x * p.x + v[r].y * p.y;
                        cim += v[r].x * p.y - v[r].y * p.x;
                        zz  += nn;
                    } else {
                        zz  -= nn;
                    }
                }
            } else {
#pragma unroll
                for (int r0 = 0; r0 < 8; r0++) {
                    if (r0 & (1 << bp)) continue;
                    int r1 = r0 | (1 << bp);
                    cre += v[r0].x * v[r1].x + v[r0].y * v[r1].y;
                    cim += v[r0].x * v[r1].y - v[r0].y * v[r1].x;
                    zz  += v[r0].x * v[r0].x + v[r0].y * v[r0].y
                         - v[r1].x * v[r1].x - v[r1].y * v[r1].y;
                }
            }
            for (int off = 16; off; off >>= 1) {
                cre += __shfl_xor_sync(0xffffffffu, cre, off);
                cim += __shfl_xor_sync(0xffffffffu, cim, off);
                zz  += __shfl_xor_sync(0xffffffffu, zz, off);
            }
            if (lane == 0) { ex[q] = 2.f * cre; ex[8 + q] = 2.f * cim; ex[16 + q] = zz; }
        }
    }
    __syncthreads();

    /* FF1 + ReLU */
    {
        float s = ff1b[tid];
#pragma unroll
        for (int m = 0; m < NM; m++) s += ex[m] * ff1W[tid * NM + m];
        g_h[b * EMB + tid] = fmaxf(s, 0.f);
    }
}

/* --------- kernel 3: FF2 direct — warp = 4 rows × 8 lanes ----------------
   Each thread: 16 LDG.128 over its k-slice, 16 packed accumulators against
   a bank-swizzled h table in smem, then 3-level shfl64 reduce over 8 lanes.
   hs slot for (kp, b) is hs[kp*16 + ((b + 2*((kp>>1)&7)) & 15)]            */
__global__ void __launch_bounds__(256) k_ff2(const float* __restrict__ ff2W,
                                             const float* __restrict__ ff2b,
                                             float* __restrict__ out,
                                             int write_mean) {
    __shared__ ull hs[256 * 16];       /* 32 KB */
    int t = threadIdx.x;

    if (blockIdx.x == 0 && t == 0 && write_mean) {
        float s = 0.f;
        for (int b = 0; b < BATCH; b++) s += g_fp[b];
        out[(size_t)BATCH * VOCAB] = s * (1.0f / BATCH);
    }

    /* stage h (swizzled); b fastest -> STS conflict-free */
    for (int idx = t; idx < 256 * 16; idx += 256) {
        int b = idx & 15, kp = idx >> 4;
        float2 hv = *reinterpret_cast<const float2*>(&g_h[b * EMB + 2 * kp]);
        int bs = (b + 2 * ((kp >> 1) & 7)) & 15;
        hs[kp * 16 + bs] = pack2(hv.x, hv.y);
    }
    __syncthreads();

    int g = t >> 3, sub = t & 7;
    int v = blockIdx.x * 32 + g;
    int vc = v < VOCAB ? v : VOCAB - 1;
    const float4* wrow = reinterpret_cast<const float4*>(ff2W + (size_t)vc * EMB);
    int s2 = 2 * sub;                  /* swizzle offset for this thread */

    ull acc[16];
#pragma unroll
    for (int b = 0; b < 16; b++) acc[b] = 0ull;

#pragma unroll
    for (int i = 0; i < 16; i++) {
        int j = sub + 8 * i;           /* float4 index in row: covers kp 2j, 2j+1 */
        float4 w4 = __ldg(&wrow[j]);
        ull w01 = pack2(w4.x, w4.y);
        ull w23 = pack2(w4.z, w4.w);
        const ull* h0 = &hs[(2 * j) * 16];
        const ull* h1 = h0 + 16;
#pragma unroll
        for (int b = 0; b < 16; b += 2) {
            int b0 = (b + s2) & 15;    /* even; slot b0 holds batch b */
            ulonglong2 hb0 = *reinterpret_cast<const ulonglong2*>(h0 + b0);
            acc[b]     = fma2(w01, hb0.x, acc[b]);
            acc[b + 1] = fma2(w01, hb0.y, acc[b + 1]);
            ulonglong2 hb1 = *reinterpret_cast<const ulonglong2*>(h1 + b0);
            acc[b]     = fma2(w23, hb1.x, acc[b]);
            acc[b + 1] = fma2(w23, hb1.y, acc[b + 1]);
        }
    }

    /* reduce across the 8 lanes of this row group */
#pragma unroll
    for (int b = 0; b < 16; b++) {
#pragma unroll
        for (int m = 1; m < 8; m <<= 1)
            acc[b] = add2(acc[b], __shfl_xor_sync(0xffffffffu, acc[b], m));
    }

    if (v < VOCAB) {
        float bias = ff2b[v];
        int b = 2 * sub;               /* each lane writes 2 batches */
        float2 p = upk2(acc[b]);
        out[(size_t)b * VOCAB + v] = p.x + p.y + bias;
        float2 q = upk2(acc[b + 1]);
        out[(size_t)(b + 1) * VOCAB + v] = q.x + q.y + bias;
    }
}

/* ---------------- launch ------------------------------------------------- */
extern "C" void kernel_launch(void* const* d_in, const int* in_sizes, int n_in,
                              void* d_out, int out_size) {
    const int*   x    = (const int*)  d_in[0];
    const float* embW = (const float*)d_in[1];
    const float* e2rW = (const float*)d_in[2];
    const float* e2rb = (const float*)d_in[3];
    const float* poly = (const float*)d_in[4];
    const float* mix  = (const float*)d_in[5];
    const float* qff  = (const float*)d_in[6];
    const float* ff1W = (const float*)d_in[7];
    const float* ff1b = (const float*)d_in[8];
    const float* ff2W = (const float*)d_in[9];
    const float* ff2b = (const float*)d_in[10];
    float* out = (float*)d_out;

    int write_mean = (out_size > BATCH * VOCAB) ? 1 : 0;

    k_nop<<<1, 32>>>();
    k_wparams<<<BATCH * NW, 256>>>(x, embW, e2rW, e2rb);
    k_mega<<<BATCH, 512>>>(poly, mix, qff, ff1W, ff1b);
    int blocks = (VOCAB + 31) / 32;
    k_ff2<<<blocks, 256>>>(ff2W, ff2b, out, write_mean);
}

// round 15
// speedup vs baseline: 1.4965x; 1.4965x over previous
#include <cuda_runtime.h>
#include <cstdint>

#define NQ     8
#define DIM    256
#define NW     16
#define BATCH  16
#define NROTS  64
#define EMB    512
#define VOCAB  50257
#define NM     24

typedef unsigned long long ull;

/* ---------------- scratch (device globals) ------------------------------- */
__device__ float  g_fp[BATCH];
__device__ float  g_h[BATCH * EMB];
__device__ float2 g_cs[BATCH * NW * NROTS];

/* ---------------- packed f32x2 helpers ----------------------------------- */
__device__ __forceinline__ ull fma2(ull a, ull b, ull c) {
    ull d;
    asm("fma.rn.f32x2 %0, %1, %2, %3;" : "=l"(d) : "l"(a), "l"(b), "l"(c));
    return d;
}
__device__ __forceinline__ float2 upk2(ull v) {
    float lo, hi;
    asm("mov.b64 {%0, %1}, %2;" : "=f"(lo), "=f"(hi) : "l"(v));
    return make_float2(lo, hi);
}
__device__ __forceinline__ ull pack2(float x, float y) {
    ull r;
    asm("mov.b64 %0, {%1, %2};" : "=l"(r) : "f"(x), "f"(y));
    return r;
}

/* ============ warp-level statevector gates (amp i = lane*8 + r) ========== */
__device__ __forceinline__ float2 shfl_xor_f2(float2 v, int m) {
    float2 r;
    r.x = __shfl_xor_sync(0xffffffffu, v.x, m);
    r.y = __shfl_xor_sync(0xffffffffu, v.y, m);
    return r;
}

template<int BP>
__device__ __forceinline__ void ry_reg(float2* v, float c, float s) {
#pragma unroll
    for (int r0 = 0; r0 < 8; r0++) {
        if (r0 & (1 << BP)) continue;
        const int r1 = r0 | (1 << BP);
        float2 a0 = v[r0], a1 = v[r1];
        v[r0] = make_float2(c * a0.x - s * a1.x, c * a0.y - s * a1.y);
        v[r1] = make_float2(s * a0.x + c * a1.x, s * a0.y + c * a1.y);
    }
}
template<int LB>
__device__ __forceinline__ void ry_lane(float2* v, float c, float s, int lane) {
    float ss = ((lane >> LB) & 1) ? s : -s;
#pragma unroll
    for (int r = 0; r < 8; r++) {
        float2 p = shfl_xor_f2(v[r], 1 << LB);
        v[r].x = c * v[r].x + ss * p.x;
        v[r].y = c * v[r].y + ss * p.y;
    }
}
template<int BC, int BT>
__device__ __forceinline__ void crx_rr(float2* v, float c, float s) {
#pragma unroll
    for (int r0 = 0; r0 < 8; r0++) {
        if (!(r0 & (1 << BC)) || (r0 & (1 << BT))) continue;
        const int r1 = r0 | (1 << BT);
        float2 a0 = v[r0], a1 = v[r1];
        v[r0] = make_float2(c * a0.x + s * a1.y, c * a0.y - s * a1.x);
        v[r1] = make_float2(s * a0.y + c * a1.x, -s * a0.x + c * a1.y);
    }
}
template<int LC, int BT>
__device__ __forceinline__ void crx_lr(float2* v, float c, float s, int lane) {
    if ((lane >> LC) & 1) {
#pragma unroll
        for (int r0 = 0; r0 < 8; r0++) {
            if (r0 & (1 << BT)) continue;
            const int r1 = r0 | (1 << BT);
            float2 a0 = v[r0], a1 = v[r1];
            v[r0] = make_float2(c * a0.x + s * a1.y, c * a0.y - s * a1.x);
            v[r1] = make_float2(s * a0.y + c * a1.x, -s * a0.x + c * a1.y);
        }
    }
}
template<int BC, int LT>
__device__ __forceinline__ void crx_rl(float2* v, float c, float s) {
#pragma unroll
    for (int r = 0; r < 8; r++) {
        if (!(r & (1 << BC))) continue;
        float2 p = shfl_xor_f2(v[r], 1 << LT);
        float2 a = v[r];
        v[r].x = c * a.x + s * p.y;
        v[r].y = c * a.y - s * p.x;
    }
}
template<int LC, int LT>
__device__ __forceinline__ void crx_ll(float2* v, float c, float s, int lane) {
    bool act = (lane >> LC) & 1;
#pragma unroll
    for (int r = 0; r < 8; r++) {
        float2 p = shfl_xor_f2(v[r], 1 << LT);
        if (act) {
            float2 a = v[r];
            v[r].x = c * a.x + s * p.y;
            v[r].y = c * a.y - s * p.x;
        }
    }
}

__device__ __forceinline__ void sim_layer(float2* v, const float2* cs, int lane) {
    float2 g;
    g = cs[0];  ry_lane<4>(v, g.x, g.y, lane);
    g = cs[1];  ry_lane<3>(v, g.x, g.y, lane);
    g = cs[2];  ry_lane<2>(v, g.x, g.y, lane);
    g = cs[3];  ry_lane<1>(v, g.x, g.y, lane);
    g = cs[4];  ry_lane<0>(v, g.x, g.y, lane);
    g = cs[5];  ry_reg<2>(v, g.x, g.y);
    g = cs[6];  ry_reg<1>(v, g.x, g.y);
    g = cs[7];  ry_reg<0>(v, g.x, g.y);
    g = cs[8];  crx_rl<0, 4>(v, g.x, g.y);
    g = cs[9];  crx_rr<1, 0>(v, g.x, g.y);
    g = cs[10]; crx_rr<2, 1>(v, g.x, g.y);
    g = cs[11]; crx_lr<0, 2>(v, g.x, g.y, lane);
    g = cs[12]; crx_ll<1, 0>(v, g.x, g.y, lane);
    g = cs[13]; crx_ll<2, 1>(v, g.x, g.y, lane);
    g = cs[14]; crx_ll<3, 2>(v, g.x, g.y, lane);
    g = cs[15]; crx_ll<4, 3>(v, g.x, g.y, lane);
    g = cs[16]; ry_lane<4>(v, g.x, g.y, lane);
    g = cs[17]; ry_lane<3>(v, g.x, g.y, lane);
    g = cs[18]; ry_lane<2>(v, g.x, g.y, lane);
    g = cs[19]; ry_lane<1>(v, g.x, g.y, lane);
    g = cs[20]; ry_lane<0>(v, g.x, g.y, lane);
    g = cs[21]; ry_reg<2>(v, g.x, g.y);
    g = cs[22]; ry_reg<1>(v, g.x, g.y);
    g = cs[23]; ry_reg<0>(v, g.x, g.y);
    g = cs[24]; crx_rr<0, 1>(v, g.x, g.y);
    g = cs[25]; crx_lr<4, 0>(v, g.x, g.y, lane);
    g = cs[26]; crx_ll<3, 4>(v, g.x, g.y, lane);
    g = cs[27]; crx_ll<2, 3>(v, g.x, g.y, lane);
    g = cs[28]; crx_ll<1, 2>(v, g.x, g.y, lane);
    g = cs[29]; crx_ll<0, 1>(v, g.x, g.y, lane);
    g = cs[30]; crx_rl<2, 0>(v, g.x, g.y);
    g = cs[31]; crx_rr<1, 2>(v, g.x, g.y);
}

/* --------- kernel 1: wparams — 32 warps/block, warp = 2 rots ------------- */
__global__ void __launch_bounds__(1024) k_wparams(const int* __restrict__ x,
                                                  const float* __restrict__ embW,
                                                  const float* __restrict__ e2rW,
                                                  const float* __restrict__ e2rb) {
    int bw = blockIdx.x, tid = threadIdx.x;
    int w = tid >> 5, lane = tid & 31;
    __shared__ float emb[EMB];
    int tok = __ldg(&x[bw]);
    if (tid < 128)
        reinterpret_cast<float4*>(emb)[tid] =
            reinterpret_cast<const float4*>(embW + (size_t)tok * EMB)[tid];
    __syncthreads();

    const float4* es = reinterpret_cast<const float4*>(emb);
    float4 e0 = es[lane], e1 = es[lane + 32], e2 = es[lane + 64], e3 = es[lane + 96];

    int ra = w * 2;
    const float4* wa = reinterpret_cast<const float4*>(e2rW + (size_t)ra * EMB);
    const float4* wb = reinterpret_cast<const float4*>(e2rW + (size_t)(ra + 1) * EMB);
    float4 a0 = __ldg(&wa[lane]),      a1 = __ldg(&wa[lane + 32]);
    float4 a2 = __ldg(&wa[lane + 64]), a3 = __ldg(&wa[lane + 96]);
    float4 b0 = __ldg(&wb[lane]),      b1 = __ldg(&wb[lane + 32]);
    float4 b2 = __ldg(&wb[lane + 64]), b3 = __ldg(&wb[lane + 96]);
    float accA = a0.x*e0.x + a0.y*e0.y + a0.z*e0.z + a0.w*e0.w
               + a1.x*e1.x + a1.y*e1.y + a1.z*e1.z + a1.w*e1.w
               + a2.x*e2.x + a2.y*e2.y + a2.z*e2.z + a2.w*e2.w
               + a3.x*e3.x + a3.y*e3.y + a3.z*e3.z + a3.w*e3.w;
    float accB = b0.x*e0.x + b0.y*e0.y + b0.z*e0.z + b0.w*e0.w
               + b1.x*e1.x + b1.y*e1.y + b1.z*e1.z + b1.w*e1.w
               + b2.x*e2.x + b2.y*e2.y + b2.z*e2.z + b2.w*e2.w
               + b3.x*e3.x + b3.y*e3.y + b3.z*e3.z + b3.w*e3.w;
#pragma unroll
    for (int off = 16; off; off >>= 1) {
        accA += __shfl_xor_sync(0xffffffffu, accA, off);
        accB += __shfl_xor_sync(0xffffffffu, accB, off);
    }
    if (lane == 0) {
        float pa = accA + e2rb[ra];
        float pb = accB + e2rb[ra + 1];
        g_cs[bw * NROTS + ra]     = make_float2(cosf(0.5f * pa), sinf(0.5f * pa));
        g_cs[bw * NROTS + ra + 1] = make_float2(cosf(0.5f * pb), sinf(0.5f * pb));
    }
}

/* --------- kernel 2: mega (sim 3 degrees + finalize + measure + FF1) ----- */
__global__ void __launch_bounds__(512) k_mega(
    const float* __restrict__ poly,
    const float* __restrict__ mix,
    const float* __restrict__ qff,
    const float* __restrict__ ff1W,
    const float* __restrict__ ff1b)
{
    int b = blockIdx.x, tid = threadIdx.x;
    int w = tid >> 5, lane = tid & 31;

    __shared__ float2 st_sh[NW * DIM];
    __shared__ float2 cs_sh[NW * NROTS];
    __shared__ float2 work[DIM];
    __shared__ float2 acc[DIM];
    __shared__ float2 coeffs[NW];
    __shared__ float2 csf[32];
    __shared__ float  red[8];
    __shared__ float  ex[NM];
    __shared__ float  inv_nrm_sh;

    for (int i = tid; i < NW * NROTS; i += 512)
        cs_sh[i] = g_cs[b * NW * NROTS + i];
    if (tid == 0) {
        float ssum = 0.f;
        for (int k = 0; k < NW; k++) {
            float re = mix[2 * k], im = mix[2 * k + 1];
            ssum += sqrtf(re * re + im * im);
        }
        float inv = 1.0f / fmaxf(ssum, 1e-12f);
        for (int k = 0; k < NW; k++)
            coeffs[k] = make_float2(mix[2 * k] * inv, mix[2 * k + 1] * inv);
    }
    if (tid < 32) {
        float p = qff[tid];
        csf[tid] = make_float2(cosf(0.5f * p), sinf(0.5f * p));
    }
    float p0 = poly[0], p1 = poly[1], p2 = poly[2], p3 = poly[3];
    if (tid < DIM) {
        bool z = (tid == 0);
        work[tid] = z ? make_float2(1.f, 0.f) : make_float2(0.f, 0.f);
        acc[tid]  = z ? make_float2(p0, 0.f)  : make_float2(0.f, 0.f);
    }
    __syncthreads();

#pragma unroll 1
    for (int d = 1; d <= 3; d++) {
        float pd = (d == 1) ? p1 : ((d == 2) ? p2 : p3);
        float2 v[8];
#pragma unroll
        for (int r = 0; r < 8; r++) v[r] = work[lane * 8 + r];

        sim_layer(v, cs_sh + w * NROTS, lane);
        sim_layer(v, cs_sh + w * NROTS + 32, lane);

#pragma unroll
        for (int r = 0; r < 8; r++) st_sh[w * DIM + lane * 8 + r] = v[r];
        __syncthreads();

        if (tid < DIM) {
            float2 s = make_float2(0.f, 0.f);
#pragma unroll
            for (int w2 = 0; w2 < NW; w2++) {
                float2 cw = coeffs[w2];
                float2 u  = st_sh[w2 * DIM + tid];
                s.x += cw.x * u.x - cw.y * u.y;
                s.y += cw.x * u.y + cw.y * u.x;
            }
            work[tid] = s;
            float2 a = acc[tid];
            a.x += pd * s.x; a.y += pd * s.y;
            acc[tid] = a;
        }
        __syncthreads();
    }

    /* normalize */
    float psum = fabsf(p0) + fabsf(p1) + fabsf(p2) + fabsf(p3);
    float inv1 = 1.0f / psum;
    float2 a2 = make_float2(0.f, 0.f);
    float nv = 0.f;
    if (tid < DIM) {
        a2 = acc[tid];
        a2.x *= inv1; a2.y *= inv1;
        nv = a2.x * a2.x + a2.y * a2.y;
    }
    for (int off = 16; off; off >>= 1) nv += __shfl_xor_sync(0xffffffffu, nv, off);
    if (tid < DIM && lane == 0) red[w] = nv;
    __syncthreads();
    if (tid == 0) {
        float s = 0.f;
        for (int k = 0; k < 8; k++) s += red[k];
        float nm = sqrtf(s);
        g_fp[b] = nm;
        inv_nrm_sh = 1.0f / fmaxf(nm, 1e-12f);
    }
    __syncthreads();
    float inv2 = inv_nrm_sh;
    if (tid < DIM) st_sh[tid] = make_float2(a2.x * inv2, a2.y * inv2);
    __syncthreads();

    /* final 32-gate circuit + measurement: warp 0 only */
    if (w == 0) {
        float2 v[8];
#pragma unroll
        for (int r = 0; r < 8; r++) v[r] = st_sh[lane * 8 + r];
        sim_layer(v, csf, lane);

        for (int q = 0; q < NQ; q++) {
            int bp = 7 - q;
            float cre = 0.f, cim = 0.f, zz = 0.f;
            if (bp >= 3) {
                int lb = bp - 3;
                int tb = (lane >> lb) & 1;
#pragma unroll
                for (int r = 0; r < 8; r++) {
                    float2 p = shfl_xor_f2(v[r], 1 << lb);
                    float nn = v[r].x * v[r].x + v[r].y * v[r].y;
                    if (tb == 0) {
                        cre += v[r].x * p.x + v[r].y * p.y;
                        cim += v[r].x * p.y - v[r].y * p.x;
                        zz  += nn;
                    } else {
                        zz  -= nn;
                    }
                }
            } else {
#pragma unroll
                for (int r0 = 0; r0 < 8; r0++) {
                    if (r0 & (1 << bp)) continue;
                    int r1 = r0 | (1 << bp);
                    cre += v[r0].x * v[r1].x + v[r0].y * v[r1].y;
                    cim += v[r0].x * v[r1].y - v[r0].y * v[r1].x;
                    zz  += v[r0].x * v[r0].x + v[r0].y * v[r0].y
                         - v[r1].x * v[r1].x - v[r1].y * v[r1].y;
                }
            }
            for (int off = 16; off; off >>= 1) {
                cre += __shfl_xor_sync(0xffffffffu, cre, off);
                cim += __shfl_xor_sync(0xffffffffu, cim, off);
                zz  += __shfl_xor_sync(0xffffffffu, zz, off);
            }
            if (lane == 0) { ex[q] = 2.f * cre; ex[8 + q] = 2.f * cim; ex[16 + q] = zz; }
        }
    }
    __syncthreads();

    /* FF1 + ReLU */
    {
        float s = ff1b[tid];
#pragma unroll
        for (int m = 0; m < NM; m++) s += ex[m] * ff1W[tid * NM + m];
        g_h[b * EMB + tid] = fmaxf(s, 0.f);
    }
}

/* --------- kernel 3: FF2 — 2 rows/thread, h as [batch][kp] ---------------
   warp = 4 row-groups × 8 k-lanes; row-group = 2 adjacent vocab rows.
   LDS.128 fetches (kp-pair, one batch) -> feeds 4 fma2 (2 rows × 2 kp).
   Lanes read 128B contiguous; row-groups broadcast -> conflict-free.       */
__global__ void __launch_bounds__(256) k_ff2(const float* __restrict__ ff2W,
                                             const float* __restrict__ ff2b,
                                             float* __restrict__ out,
                                             int write_mean) {
    __shared__ ull hs[BATCH * 256];    /* [b][kp] packed pairs, 32 KB */
    int t = threadIdx.x;

    if (blockIdx.x == 0 && t == 0 && write_mean) {
        float s = 0.f;
        for (int b = 0; b < BATCH; b++) s += g_fp[b];
        out[(size_t)BATCH * VOCAB] = s * (1.0f / BATCH);
    }

    for (int idx = t; idx < BATCH * 256; idx += 256) {
        int b = idx >> 8, kp = idx & 255;
        float2 hv = *reinterpret_cast<const float2*>(&g_h[b * EMB + 2 * kp]);
        hs[idx] = pack2(hv.x, hv.y);
    }
    __syncthreads();

    int warp = t >> 5, lane = t & 31;
    int rg = lane >> 3, sub = lane & 7;
    int v0 = blockIdx.x * 64 + warp * 8 + rg * 2;   /* rows v0, v0+1 */
    int vc0 = v0     < VOCAB ? v0     : VOCAB - 1;
    int vc1 = v0 + 1 < VOCAB ? v0 + 1 : VOCAB - 1;
    const float4* w0p = reinterpret_cast<const float4*>(ff2W + (size_t)vc0 * EMB);
    const float4* w1p = reinterpret_cast<const float4*>(ff2W + (size_t)vc1 * EMB);

    ull accA[BATCH], accB[BATCH];
#pragma unroll
    for (int b = 0; b < BATCH; b++) { accA[b] = 0ull; accB[b] = 0ull; }

    float4 wa = __ldg(&w0p[sub]);
    float4 wb = __ldg(&w1p[sub]);

#pragma unroll 1
    for (int i = 0; i < 16; i++) {
        int j = sub + 8 * i;
        ull a01 = pack2(wa.x, wa.y), a23 = pack2(wa.z, wa.w);
        ull b01 = pack2(wb.x, wb.y), b23 = pack2(wb.z, wb.w);
        if (i < 15) {                   /* prefetch next chunk */
            wa = __ldg(&w0p[j + 8]);
            wb = __ldg(&w1p[j + 8]);
        }
        const ull* hp = hs + 2 * j;
#pragma unroll
        for (int b = 0; b < BATCH; b++) {
            ulonglong2 h2 = *reinterpret_cast<const ulonglong2*>(hp + b * 256);
            accA[b] = fma2(a01, h2.x, accA[b]);
            accA[b] = fma2(a23, h2.y, accA[b]);
            accB[b] = fma2(b01, h2.x, accB[b]);
            accB[b] = fma2(b23, h2.y, accB[b]);
        }
    }

    /* collapse packed pairs, then reduce across the 8 k-lanes */
    float ra[BATCH], rb[BATCH];
#pragma unroll
    for (int b = 0; b < BATCH; b++) {
        float2 pa = upk2(accA[b]); ra[b] = pa.x + pa.y;
        float2 pb = upk2(accB[b]); rb[b] = pb.x + pb.y;
    }
#pragma unroll
    for (int b = 0; b < BATCH; b++) {
#pragma unroll
        for (int m = 1; m < 8; m <<= 1) {
            ra[b] += __shfl_xor_sync(0xffffffffu, ra[b], m);
            rb[b] += __shfl_xor_sync(0xffffffffu, rb[b], m);
        }
    }

    /* lane sub writes batches sub and sub+8, both rows */
    if (v0 < VOCAB) {
        float bias0 = ff2b[v0];
        int b0 = sub, b1 = sub + 8;
        out[(size_t)b0 * VOCAB + v0] = ra[b0] + bias0;
        out[(size_t)b1 * VOCAB + v0] = ra[b1] + bias0;
        if (v0 + 1 < VOCAB) {
            float bias1 = ff2b[v0 + 1];
            out[(size_t)b0 * VOCAB + v0 + 1] = rb[b0] + bias1;
            out[(size_t)b1 * VOCAB + v0 + 1] = rb[b1] + bias1;
        }
    }
}

/* ---------------- launch ------------------------------------------------- */
extern "C" void kernel_launch(void* const* d_in, const int* in_sizes, int n_in,
                              void* d_out, int out_size) {
    const int*   x    = (const int*)  d_in[0];
    const float* embW = (const float*)d_in[1];
    const float* e2rW = (const float*)d_in[2];
    const float* e2rb = (const float*)d_in[3];
    const float* poly = (const float*)d_in[4];
    const float* mix  = (const float*)d_in[5];
    const float* qff  = (const float*)d_in[6];
    const float* ff1W = (const float*)d_in[7];
    const float* ff1b = (const float*)d_in[8];
    const float* ff2W = (const float*)d_in[9];
    const float* ff2b = (const float*)d_in[10];
    float* out = (float*)d_out;

    int write_mean = (out_size > BATCH * VOCAB) ? 1 : 0;

    k_wparams<<<BATCH * NW, 1024>>>(x, embW, e2rW, e2rb);
    k_mega<<<BATCH, 512>>>(poly, mix, qff, ff1W, ff1b);
    int blocks = (VOCAB + 63) / 64;
    k_ff2<<<blocks, 256>>>(ff2W, ff2b, out, write_mean);
}